// round 4
// baseline (speedup 1.0000x reference)
#include <cuda_runtime.h>
#include <cuda_bf16.h>
#include <cuda_fp16.h>
#include <math.h>
#include <stdint.h>

#define NN 40000
#define NE 640000
#define H  128
#define ITERS 8
#define NCTA 148
#define RPC 272          // rows per CTA (multiple of 16; 147*272 + 16 = 40000)
#define PAD 136          // bf16 element stride for both A and W rows

// smem element offsets (bf16 units)
#define WS_HI 0
#define WS_LO 17408                  // 128*136
#define AS_HI 34816
#define AS_LO (34816 + RPC * PAD)    // + 36992
#define SMEM_BYTES ((34816 + 2 * RPC * PAD) * 2)   // 217600

// ---------------- device scratch ----------------
__device__ int   g_counts[NN];
__device__ int   g_rowptr[NN + 1];
__device__ int   g_cursor[NN];
__device__ int   g_col[NE];
__device__ int   g_bsums[320];
__device__ int   g_boffs[320];
__device__ float g_xp[NN * H];
__device__ uint2 g_st0[NN * 32];
__device__ uint2 g_st1[NN * 32];
__device__ float g_h0[NN * H];
__device__ uint4 g_wbf4[4][4352];    // per slot: [hi 128x136][lo 128x136] bf16
__device__ int   g_is64;
__device__ volatile unsigned g_gen;
__device__ unsigned g_cnt;

// ---------------- CSR build ----------------
__global__ void detect_kernel(const int* ei) {
    if (threadIdx.x == 0 && blockIdx.x == 0) {
        int any = 0;
        for (int i = 0; i < 128; i++) any |= ei[2 * i + 1];
        g_is64 = (any == 0) ? 1 : 0;
    }
}
__global__ void zero_counts_kernel() {
    int i = blockIdx.x * blockDim.x + threadIdx.x;
    if (i < NN) g_counts[i] = 0;
}
__global__ void hist_kernel(const void* __restrict__ ei) {
    int e = blockIdx.x * blockDim.x + threadIdx.x;
    if (e >= NE) return;
    int d;
    if (g_is64) d = (int)((const long long*)ei)[NE + e];
    else        d = ((const int*)ei)[NE + e];
    atomicAdd(&g_counts[d], 1);
}
__global__ void bsum_kernel() {
    int i = blockIdx.x * 128 + threadIdx.x;
    int c = (i < NN) ? g_counts[i] : 0;
    for (int o = 16; o > 0; o >>= 1) c += __shfl_down_sync(~0u, c, o);
    __shared__ int ws[4];
    if ((threadIdx.x & 31) == 0) ws[threadIdx.x >> 5] = c;
    __syncthreads();
    if (threadIdx.x == 0) g_bsums[blockIdx.x] = ws[0] + ws[1] + ws[2] + ws[3];
}
__global__ void bscan_kernel() {
    __shared__ int sm[512];
    int t = threadIdx.x;
    int v = (t < 313) ? g_bsums[t] : 0;
    sm[t] = v;
    __syncthreads();
    for (int o = 1; o < 512; o <<= 1) {
        int u = (t >= o) ? sm[t - o] : 0;
        __syncthreads();
        sm[t] += u;
        __syncthreads();
    }
    if (t < 313) g_boffs[t] = sm[t] - v;
}
__global__ void rowptr_kernel() {
    int t = threadIdx.x;
    int i = blockIdx.x * 128 + t;
    int c = (i < NN) ? g_counts[i] : 0;
    int lane = t & 31, w = t >> 5;
    int v = c;
    for (int o = 1; o < 32; o <<= 1) {
        int u = __shfl_up_sync(~0u, v, o);
        if (lane >= o) v += u;
    }
    __shared__ int ws[4], wo[4];
    if (lane == 31) ws[w] = v;
    __syncthreads();
    if (t == 0) { int s = 0; for (int j = 0; j < 4; j++) { wo[j] = s; s += ws[j]; } }
    __syncthreads();
    int excl = v - c + wo[w] + g_boffs[blockIdx.x];
    if (i < NN) { g_rowptr[i] = excl; g_cursor[i] = excl; }
    if (blockIdx.x == 0 && t == 0) g_rowptr[NN] = NE;
}
__global__ void scatter_kernel(const void* __restrict__ ei) {
    int e = blockIdx.x * blockDim.x + threadIdx.x;
    if (e >= NE) return;
    int s, d;
    if (g_is64) {
        s = (int)((const long long*)ei)[e];
        d = (int)((const long long*)ei)[NE + e];
    } else {
        s = ((const int*)ei)[e];
        d = ((const int*)ei)[NE + e];
    }
    int p = atomicAdd(&g_cursor[d], 1);
    g_col[p] = s;
}

// ---------------- weight prep: fp32 -> bf16 hi/lo [n][k] padded to 136 ----------
__global__ void prep_w(const float* __restrict__ w, int trans, __nv_bfloat16* __restrict__ dst) {
    int idx = blockIdx.x * blockDim.x + threadIdx.x;
    if (idx >= H * H) return;
    int n = idx >> 7, k = idx & 127;
    float a = trans ? w[k * H + n] : w[n * H + k];
    __nv_bfloat16 hi = __float2bfloat16_rn(a);
    __nv_bfloat16 lo = __float2bfloat16_rn(a - __bfloat162float(hi));
    dst[n * PAD + k] = hi;
    dst[17408 + n * PAD + k] = lo;
}

// ---------------- mma.sync helper ----------------
__device__ __forceinline__ void mma16816(float* c, const uint32_t* a, const uint32_t* b) {
    asm volatile(
        "mma.sync.aligned.m16n8k16.row.col.f32.bf16.bf16.f32 "
        "{%0,%1,%2,%3}, {%4,%5,%6,%7}, {%8,%9}, {%0,%1,%2,%3};"
        : "+f"(c[0]), "+f"(c[1]), "+f"(c[2]), "+f"(c[3])
        : "r"(a[0]), "r"(a[1]), "r"(a[2]), "r"(a[3]), "r"(b[0]), "r"(b[1]));
}

// ---------------- grid barrier (all 148 CTAs resident: 1 CTA/SM) ----------------
__device__ __forceinline__ void gbar() {
    __syncthreads();
    if (threadIdx.x == 0) {
        __threadfence();
        unsigned gen = g_gen;
        if (atomicAdd(&g_cnt, 1) == gridDim.x - 1) {
            g_cnt = 0;
            __threadfence();
            g_gen = gen + 1;
        } else {
            while (g_gen == gen) __nanosleep(32);
        }
        __threadfence();
    }
    __syncthreads();
}

// ---------------- split helper: float4 -> bf16 hi/lo uint2 pair ------------------
__device__ __forceinline__ void split4(float4 a, uint2& hv, uint2& lv) {
    __nv_bfloat16 hx = __float2bfloat16_rn(a.x);
    __nv_bfloat16 hy = __float2bfloat16_rn(a.y);
    __nv_bfloat16 hz = __float2bfloat16_rn(a.z);
    __nv_bfloat16 hw = __float2bfloat16_rn(a.w);
    __nv_bfloat16 lx = __float2bfloat16_rn(a.x - __bfloat162float(hx));
    __nv_bfloat16 ly = __float2bfloat16_rn(a.y - __bfloat162float(hy));
    __nv_bfloat16 lz = __float2bfloat16_rn(a.z - __bfloat162float(hz));
    __nv_bfloat16 lw = __float2bfloat16_rn(a.w - __bfloat162float(hw));
    __nv_bfloat162 h01(hx, hy), h23(hz, hw), l01(lx, ly), l23(lz, lw);
    hv = make_uint2(*(uint32_t*)&h01, *(uint32_t*)&h23);
    lv = make_uint2(*(uint32_t*)&l01, *(uint32_t*)&l23);
}

// ---------------- fused persistent kernel ----------------------------------------
// smem: Ws hi/lo [128][136] + As hi/lo [272][136]
// 16 warps: nw = wid&1 (64-col half), mg = wid>>1 (m-tile group).
__global__ __launch_bounds__(512, 1)
void fused_kernel(const float* __restrict__ x, float* __restrict__ out) {
    extern __shared__ __nv_bfloat16 smem[];
    const int tid  = threadIdx.x;
    const int wid  = tid >> 5, lane = tid & 31;
    const int qg   = lane & 3, rg = lane >> 2;
    const int nw   = wid & 1, mg = wid >> 1;
    const int r0c  = blockIdx.x * RPC;
    const int r1c  = (r0c + RPC < NN) ? r0c + RPC : NN;
    const int rows = r1c - r0c;
    const int ntile = rows >> 4;      // rows always multiple of 16

    const uint4* wslots = &g_wbf4[0][0];
    uint2* st[2] = { g_st0, g_st1 };

    for (int layer = 0; layer < 2; layer++) {
        // ---- load W_in slot ----
        {
            const uint4* src = wslots + (size_t)(layer * 2) * 4352;
            uint4* d = (uint4*)smem;
#pragma unroll
            for (int i = 0; i < 9; i++) {
                int f = tid + i * 512;
                if (f < 4352) d[f] = src[f];
            }
        }
        // ---- dense A load: src rows -> bf16 split smem ----
        {
            const float* srcA = layer ? g_h0 : x;
            for (int j = wid; j < rows; j += 16) {
                float4 a = *(const float4*)(srcA + (size_t)(r0c + j) * H + lane * 4);
                uint2 hv, lv;
                split4(a, hv, lv);
                int off = j * PAD + lane * 4;
                *(uint2*)(smem + AS_HI + off) = hv;
                *(uint2*)(smem + AS_LO + off) = lv;
            }
        }
        __syncthreads();

        // ---- phase MMA: xp = A @ W_in^T ; st[0] = tanh(xp) ----
        for (int t = mg; t < ntile; t += 8) {
            float acc[8][4];
#pragma unroll
            for (int nt = 0; nt < 8; nt++)
#pragma unroll
                for (int q = 0; q < 4; q++) acc[nt][q] = 0.f;
#pragma unroll
            for (int ks = 0; ks < 8; ks++) {
                const int kk = ks * 16 + qg * 2;
                const int ra = (t * 16 + rg) * PAD;
                uint32_t ah[4], al[4];
                ah[0] = *(const uint32_t*)(smem + AS_HI + ra + kk);
                ah[1] = *(const uint32_t*)(smem + AS_HI + ra + 8 * PAD + kk);
                ah[2] = *(const uint32_t*)(smem + AS_HI + ra + kk + 8);
                ah[3] = *(const uint32_t*)(smem + AS_HI + ra + 8 * PAD + kk + 8);
                al[0] = *(const uint32_t*)(smem + AS_LO + ra + kk);
                al[1] = *(const uint32_t*)(smem + AS_LO + ra + 8 * PAD + kk);
                al[2] = *(const uint32_t*)(smem + AS_LO + ra + kk + 8);
                al[3] = *(const uint32_t*)(smem + AS_LO + ra + 8 * PAD + kk + 8);
#pragma unroll
                for (int nt = 0; nt < 8; nt++) {
                    const int n = nw * 64 + nt * 8 + rg;
                    uint32_t bh[2], bl[2];
                    bh[0] = *(const uint32_t*)(smem + WS_HI + n * PAD + kk);
                    bh[1] = *(const uint32_t*)(smem + WS_HI + n * PAD + kk + 8);
                    bl[0] = *(const uint32_t*)(smem + WS_LO + n * PAD + kk);
                    bl[1] = *(const uint32_t*)(smem + WS_LO + n * PAD + kk + 8);
                    mma16816(acc[nt], ah, bh);
                    mma16816(acc[nt], ah, bl);
                    mma16816(acc[nt], al, bh);
                }
            }
            // epilogue: write xp fp32 + st[0] = tanh fp16
#pragma unroll
            for (int half = 0; half < 2; half++) {
                const int row = r0c + t * 16 + rg + half * 8;
#pragma unroll
                for (int nt = 0; nt < 8; nt++) {
                    const int col = nw * 64 + nt * 8 + qg * 2;
                    float2 o = make_float2(acc[nt][half * 2], acc[nt][half * 2 + 1]);
                    *(float2*)(g_xp + (size_t)row * H + col) = o;
                    __half2 p = __floats2half2_rn(tanhf(o.x), tanhf(o.y));
                    *(__half2*)((__half*)st[0] + (size_t)row * H + col) = p;
                }
            }
        }
        gbar();

        // ---- load W_rec slot ----
        {
            const uint4* src = wslots + (size_t)(layer * 2 + 1) * 4352;
            uint4* d = (uint4*)smem;
#pragma unroll
            for (int i = 0; i < 9; i++) {
                int f = tid + i * 512;
                if (f < 4352) d[f] = src[f];
            }
        }

        for (int it = 0; it < ITERS; it++) {
            // ---- gather into As (bf16 split) ----
            const uint2* rd = st[it & 1];
            for (int j = wid; j < rows; j += 16) {
                const int node = r0c + j;
                const int beg = g_rowptr[node], end = g_rowptr[node + 1];
                float4 acc = make_float4(0.f, 0.f, 0.f, 0.f);
                int p = beg;
                for (; p + 1 < end; p += 2) {
                    int s0 = g_col[p], s1 = g_col[p + 1];
                    uint2 v0 = __ldg(&rd[(size_t)s0 * 32 + lane]);
                    uint2 v1 = __ldg(&rd[(size_t)s1 * 32 + lane]);
                    float2 a0 = __half22float2(*(const __half2*)&v0.x);
                    float2 b0 = __half22float2(*(const __half2*)&v0.y);
                    float2 a1 = __half22float2(*(const __half2*)&v1.x);
                    float2 b1 = __half22float2(*(const __half2*)&v1.y);
                    acc.x += a0.x + a1.x; acc.y += a0.y + a1.y;
                    acc.z += b0.x + b1.x; acc.w += b0.y + b1.y;
                }
                if (p < end) {
                    int s0 = g_col[p];
                    uint2 v0 = __ldg(&rd[(size_t)s0 * 32 + lane]);
                    float2 a0 = __half22float2(*(const __half2*)&v0.x);
                    float2 b0 = __half22float2(*(const __half2*)&v0.y);
                    acc.x += a0.x; acc.y += a0.y; acc.z += b0.x; acc.w += b0.y;
                }
                uint2 hv, lv;
                split4(acc, hv, lv);
                int off = j * PAD + lane * 4;
                *(uint2*)(smem + AS_HI + off) = hv;
                *(uint2*)(smem + AS_LO + off) = lv;
            }
            __syncthreads();

            // ---- MMA + fused epilogue ----
            const bool last = (it == ITERS - 1);
            for (int t = mg; t < ntile; t += 8) {
                float acc[8][4];
#pragma unroll
                for (int nt = 0; nt < 8; nt++)
#pragma unroll
                    for (int q = 0; q < 4; q++) acc[nt][q] = 0.f;
#pragma unroll
                for (int ks = 0; ks < 8; ks++) {
                    const int kk = ks * 16 + qg * 2;
                    const int ra = (t * 16 + rg) * PAD;
                    uint32_t ah[4], al[4];
                    ah[0] = *(const uint32_t*)(smem + AS_HI + ra + kk);
                    ah[1] = *(const uint32_t*)(smem + AS_HI + ra + 8 * PAD + kk);
                    ah[2] = *(const uint32_t*)(smem + AS_HI + ra + kk + 8);
                    ah[3] = *(const uint32_t*)(smem + AS_HI + ra + 8 * PAD + kk + 8);
                    al[0] = *(const uint32_t*)(smem + AS_LO + ra + kk);
                    al[1] = *(const uint32_t*)(smem + AS_LO + ra + 8 * PAD + kk);
                    al[2] = *(const uint32_t*)(smem + AS_LO + ra + kk + 8);
                    al[3] = *(const uint32_t*)(smem + AS_LO + ra + 8 * PAD + kk + 8);
#pragma unroll
                    for (int nt = 0; nt < 8; nt++) {
                        const int n = nw * 64 + nt * 8 + rg;
                        uint32_t bh[2], bl[2];
                        bh[0] = *(const uint32_t*)(smem + WS_HI + n * PAD + kk);
                        bh[1] = *(const uint32_t*)(smem + WS_HI + n * PAD + kk + 8);
                        bl[0] = *(const uint32_t*)(smem + WS_LO + n * PAD + kk);
                        bl[1] = *(const uint32_t*)(smem + WS_LO + n * PAD + kk + 8);
                        mma16816(acc[nt], ah, bh);
                        mma16816(acc[nt], ah, bl);
                        mma16816(acc[nt], al, bh);
                    }
                }
#pragma unroll
                for (int half = 0; half < 2; half++) {
                    const int row = r0c + t * 16 + rg + half * 8;
#pragma unroll
                    for (int nt = 0; nt < 8; nt++) {
                        const int col = nw * 64 + nt * 8 + qg * 2;
                        float2 xv = *(const float2*)(g_xp + (size_t)row * H + col);
                        float2 o = make_float2(tanhf(acc[nt][half * 2] + xv.x),
                                               tanhf(acc[nt][half * 2 + 1] + xv.y));
                        if (!last) {
                            __half2 p = __floats2half2_rn(o.x, o.y);
                            *(__half2*)((__half*)st[(it + 1) & 1] + (size_t)row * H + col) = p;
                        } else if (layer == 0) {
                            *(float2*)(g_h0 + (size_t)row * H + col) = o;
                        } else {
                            *(float2*)(out + (size_t)row * H + col) = o;
                        }
                    }
                }
            }
            gbar();
        }
    }
}

// ---------------- launcher ----------------
extern "C" void kernel_launch(void* const* d_in, const int* in_sizes, int n_in,
                              void* d_out, int out_size) {
    const void*  ei     = d_in[0];
    const float* x      = (const float*)d_in[1];
    const float* w_in0  = (const float*)d_in[2];
    const float* w_rec0 = (const float*)d_in[3];
    const float* w_in1  = (const float*)d_in[4];
    const float* w_rec1 = (const float*)d_in[5];
    float*       out    = (float*)d_out;

    void* pwb;
    cudaGetSymbolAddress(&pwb, g_wbf4);
    __nv_bfloat16* wbf = (__nv_bfloat16*)pwb;

    cudaFuncSetAttribute(fused_kernel, cudaFuncAttributeMaxDynamicSharedMemorySize, SMEM_BYTES);

    // ---- CSR build ----
    const int GB = (NN + 127) / 128;
    detect_kernel<<<1, 32>>>((const int*)ei);
    zero_counts_kernel<<<(NN + 255) / 256, 256>>>();
    hist_kernel<<<(NE + 255) / 256, 256>>>(ei);
    bsum_kernel<<<GB, 128>>>();
    bscan_kernel<<<1, 512>>>();
    rowptr_kernel<<<GB, 128>>>();
    scatter_kernel<<<(NE + 255) / 256, 256>>>(ei);

    // ---- weight prep: slots: 0=w_in0, 1=w_rec0, 2=w_in1, 3=w_rec1 ----
    prep_w<<<64, 256>>>(w_in0,  0, wbf + 0 * 34816);
    prep_w<<<64, 256>>>(w_rec0, 1, wbf + 1 * 34816);
    prep_w<<<64, 256>>>(w_in1,  0, wbf + 2 * 34816);
    prep_w<<<64, 256>>>(w_rec1, 1, wbf + 3 * 34816);

    // ---- fused persistent kernel ----
    fused_kernel<<<NCTA, 512, SMEM_BYTES>>>(x, out);
}